// round 1
// baseline (speedup 1.0000x reference)
#include <cuda_runtime.h>
#include <cstdint>

// Problem constants
#define BB 32
#define SS 2048
#define DD 64
#define TQ 64
#define TK 64
#define NKT (SS / TK)      // 32 key tiles
#define NTHREADS 256

// smem strides (floats)
#define STQ 68   // Qs_t [D][STQ]  (col = query i), float4 reads -> mult of 4
#define STK 65   // Ks   [TK][STK] (scalar access, +1 pad -> 2-way worst)
#define STV 68   // Vs   [TK][STV] float4 access
#define STE 68   // Es   [TQ][STE] float4 writes, scalar reads

#define SMEM_BYTES ((DD*STQ + TK*STK + TK*STV + TQ*STE + 16*TQ + TQ) * 4)

// scratch: inverse row sums (256 KB) — device global, no allocation
__device__ float g_invl[BB * SS];

__global__ void __launch_bounds__(NTHREADS)
attn_main_kernel(const float* __restrict__ q,
                 const float* __restrict__ k,
                 const float* __restrict__ v,
                 float* __restrict__ out,
                 float* __restrict__ attn)
{
    extern __shared__ float smem[];
    float* sQ   = smem;                      // [DD][STQ]  transposed Q
    float* sK   = sQ + DD * STQ;             // [TK][STK]
    float* sV   = sK + TK * STK;             // [TK][STV]
    float* sE   = sV + TK * STV;             // [TQ][STE]
    float* lred = sE + TQ * STE;             // [16][TQ]
    float* sl   = lred + 16 * TQ;            // [TQ] inverse row sums

    const int tid = threadIdx.x;
    const int tx  = tid & 15;    // 16 groups
    const int ty  = tid >> 4;    // 16 groups
    const int qt  = blockIdx.x;
    const int b   = blockIdx.y;
    const int qbase = qt * TQ;

    // ---- load Q tile transposed: sQ[d][i] ----
    {
        const float* qg = q + ((size_t)b * SS + qbase) * DD;
        #pragma unroll
        for (int it = 0; it < 4; ++it) {
            int idx = tid + it * NTHREADS;      // 0..1023
            int i  = idx >> 4;
            int d4 = (idx & 15) << 2;
            float4 qv = *(const float4*)&qg[(size_t)i * DD + d4];
            sQ[(d4 + 0) * STQ + i] = qv.x;
            sQ[(d4 + 1) * STQ + i] = qv.y;
            sQ[(d4 + 2) * STQ + i] = qv.z;
            sQ[(d4 + 3) * STQ + i] = qv.w;
        }
    }

    float o[4][4];
    #pragma unroll
    for (int a = 0; a < 4; ++a)
        #pragma unroll
        for (int c = 0; c < 4; ++c) o[a][c] = 0.f;

    float ls[4] = {0.f, 0.f, 0.f, 0.f};

    const float CEXP = 0.125f * 1.44269504f;   // /8 then log2(e) for exp2f

    for (int kt = 0; kt < NKT; ++kt) {
        const int kbase = kt * TK;
        __syncthreads();   // previous PV done before overwriting sK/sV/sE

        // ---- load K (scalar-store, pad 65) and V (float4) tiles ----
        {
            const float* kg = k + ((size_t)b * SS + kbase) * DD;
            const float* vg = v + ((size_t)b * SS + kbase) * DD;
            #pragma unroll
            for (int it = 0; it < 4; ++it) {
                int idx = tid + it * NTHREADS;
                int j  = idx >> 4;
                int d4 = (idx & 15) << 2;
                float4 kv = *(const float4*)&kg[(size_t)j * DD + d4];
                sK[j * STK + d4 + 0] = kv.x;
                sK[j * STK + d4 + 1] = kv.y;
                sK[j * STK + d4 + 2] = kv.z;
                sK[j * STK + d4 + 3] = kv.w;
                float4 vv = *(const float4*)&vg[(size_t)j * DD + d4];
                *(float4*)&sV[j * STV + d4] = vv;
            }
        }
        __syncthreads();

        // ---- scores: 64x64 block, thread = 4 rows (ty) x 4 cols (tx) ----
        float acc[4][4];
        #pragma unroll
        for (int a = 0; a < 4; ++a)
            #pragma unroll
            for (int c = 0; c < 4; ++c) acc[a][c] = 0.f;

        #pragma unroll 8
        for (int d = 0; d < DD; ++d) {
            float4 av = *(const float4*)&sQ[d * STQ + (ty << 2)];
            float b0 = sK[((tx << 2) + 0) * STK + d];
            float b1 = sK[((tx << 2) + 1) * STK + d];
            float b2 = sK[((tx << 2) + 2) * STK + d];
            float b3 = sK[((tx << 2) + 3) * STK + d];
            acc[0][0] += av.x * b0; acc[0][1] += av.x * b1; acc[0][2] += av.x * b2; acc[0][3] += av.x * b3;
            acc[1][0] += av.y * b0; acc[1][1] += av.y * b1; acc[1][2] += av.y * b2; acc[1][3] += av.y * b3;
            acc[2][0] += av.z * b0; acc[2][1] += av.z * b1; acc[2][2] += av.z * b2; acc[2][3] += av.z * b3;
            acc[3][0] += av.w * b0; acc[3][1] += av.w * b1; acc[3][2] += av.w * b2; acc[3][3] += av.w * b3;
        }

        // ---- exp, row-sum partials, stage to sE, stream unnormalized to gmem ----
        #pragma unroll
        for (int ii = 0; ii < 4; ++ii) {
            float4 e4;
            e4.x = exp2f(acc[ii][0] * CEXP);
            e4.y = exp2f(acc[ii][1] * CEXP);
            e4.z = exp2f(acc[ii][2] * CEXP);
            e4.w = exp2f(acc[ii][3] * CEXP);
            ls[ii] += (e4.x + e4.y) + (e4.z + e4.w);
            *(float4*)&sE[((ty << 2) + ii) * STE + (tx << 2)] = e4;
            size_t arow = ((size_t)b * SS + qbase + (ty << 2) + ii) * (size_t)SS
                          + kbase + (tx << 2);
            *(float4*)&attn[arow] = e4;   // unnormalized; fixed by normalize kernel
        }
        __syncthreads();

        // ---- O += E @ V : thread = 4 rows (ty) x 4 dims (tx) ----
        #pragma unroll 8
        for (int j = 0; j < TK; ++j) {
            float4 bv = *(const float4*)&sV[j * STV + (tx << 2)];
            float a0 = sE[((ty << 2) + 0) * STE + j];
            float a1 = sE[((ty << 2) + 1) * STE + j];
            float a2 = sE[((ty << 2) + 2) * STE + j];
            float a3 = sE[((ty << 2) + 3) * STE + j];
            o[0][0] += a0 * bv.x; o[0][1] += a0 * bv.y; o[0][2] += a0 * bv.z; o[0][3] += a0 * bv.w;
            o[1][0] += a1 * bv.x; o[1][1] += a1 * bv.y; o[1][2] += a1 * bv.z; o[1][3] += a1 * bv.w;
            o[2][0] += a2 * bv.x; o[2][1] += a2 * bv.y; o[2][2] += a2 * bv.z; o[2][3] += a2 * bv.w;
            o[3][0] += a3 * bv.x; o[3][1] += a3 * bv.y; o[3][2] += a3 * bv.z; o[3][3] += a3 * bv.w;
        }
    }

    // ---- reduce row sums across the 16 tx groups ----
    #pragma unroll
    for (int ii = 0; ii < 4; ++ii)
        lred[tx * TQ + (ty << 2) + ii] = ls[ii];
    __syncthreads();
    if (tid < TQ) {
        float s = 0.f;
        #pragma unroll
        for (int g = 0; g < 16; ++g) s += lred[g * TQ + tid];
        float inv = 1.0f / s;
        sl[tid] = inv;
        g_invl[(size_t)b * SS + qbase + tid] = inv;
    }
    __syncthreads();

    // ---- write normalized output ----
    #pragma unroll
    for (int ii = 0; ii < 4; ++ii) {
        float inv = sl[(ty << 2) + ii];
        float4 ov;
        ov.x = o[ii][0] * inv; ov.y = o[ii][1] * inv;
        ov.z = o[ii][2] * inv; ov.w = o[ii][3] * inv;
        size_t orow = ((size_t)b * SS + qbase + (ty << 2) + ii) * DD + (tx << 2);
        *(float4*)&out[orow] = ov;
    }
}

// Rescale attn rows by 1/l (attn was written unnormalized).
__global__ void __launch_bounds__(256)
attn_normalize_kernel(float* __restrict__ attn)
{
    size_t idx = (size_t)blockIdx.x * blockDim.x + threadIdx.x;  // float4 index
    size_t row = idx >> 9;            // (idx*4)/2048
    float inv = g_invl[row];
    float4* p = (float4*)attn;
    float4 vv = p[idx];
    vv.x *= inv; vv.y *= inv; vv.z *= inv; vv.w *= inv;
    p[idx] = vv;
}

extern "C" void kernel_launch(void* const* d_in, const int* in_sizes, int n_in,
                              void* d_out, int out_size)
{
    const float* q = (const float*)d_in[0];
    const float* k = (const float*)d_in[1];
    const float* v = (const float*)d_in[2];
    float* out  = (float*)d_out;                       // [B,S,D] first
    float* attn = out + (size_t)BB * SS * DD;          // then [B,S,S]

    cudaFuncSetAttribute(attn_main_kernel,
                         cudaFuncAttributeMaxDynamicSharedMemorySize, SMEM_BYTES);

    dim3 grid(SS / TQ, BB);
    attn_main_kernel<<<grid, NTHREADS, SMEM_BYTES>>>(q, k, v, out, attn);

    size_t nq4 = (size_t)BB * SS * SS / 4;             // 33,554,432 float4
    attn_normalize_kernel<<<(unsigned)(nq4 / 256), 256>>>(attn);
}

// round 3
// speedup vs baseline: 3.1867x; 3.1867x over previous
#include <cuda_runtime.h>
#include <cstdint>

#define BB 32
#define SS 2048
#define DDIM 64
#define TQ 64
#define TK 64
#define NKT 32
#define NTH 256

// bf16 tile row stride: 72 elems = 144 bytes (16B-aligned, ldmatrix conflict-free)
#define RS 144
// smem byte offsets
#define OQHI 0u
#define OQLO 9216u
#define OKHI 18432u
#define OKLO 27648u
#define OVHI 36864u
#define OVLO 46080u
#define SMEMSZ 55296u
// epilogue reduce area reuses the Q region [0, 18432)
#define ORED  0u        // fp32 [64][68] O partials
#define OLBUF 17408u    // fp32 [128] row-sum partials
#define OLINV 17920u    // fp32 [64] inverse row sums

__device__ float g_invl[BB * SS];

// ---------------- helpers ----------------
__device__ __forceinline__ uint32_t s2u(const void* p) {
    uint32_t a;
    asm("{ .reg .u64 t; cvta.to.shared.u64 t, %1; cvt.u32.u64 %0, t; }" : "=r"(a) : "l"(p));
    return a;
}
// split pair (a,b) -> packed bf16x2 hi (a in low half) and packed lo residuals
__device__ __forceinline__ void split2(float a, float b, uint32_t& hi, uint32_t& lo) {
    uint32_t h;
    asm("cvt.rn.bf16x2.f32 %0, %1, %2;" : "=r"(h) : "f"(b), "f"(a));
    float fa = __uint_as_float(h << 16);
    float fb = __uint_as_float(h & 0xFFFF0000u);
    float la = a - fa, lb = b - fb;
    asm("cvt.rn.bf16x2.f32 %0, %1, %2;" : "=r"(lo) : "f"(lb), "f"(la));
    hi = h;
}
__device__ __forceinline__ uint32_t packbf(float lo_e, float hi_e) {
    uint32_t r;
    asm("cvt.rn.bf16x2.f32 %0, %1, %2;" : "=r"(r) : "f"(hi_e), "f"(lo_e));
    return r;
}
__device__ __forceinline__ void ldm4(uint32_t& r0, uint32_t& r1, uint32_t& r2, uint32_t& r3, uint32_t a) {
    asm volatile("ldmatrix.sync.aligned.m8n8.x4.shared.b16 {%0,%1,%2,%3}, [%4];"
                 : "=r"(r0), "=r"(r1), "=r"(r2), "=r"(r3) : "r"(a));
}
__device__ __forceinline__ void ldm4t(uint32_t& r0, uint32_t& r1, uint32_t& r2, uint32_t& r3, uint32_t a) {
    asm volatile("ldmatrix.sync.aligned.m8n8.x4.trans.shared.b16 {%0,%1,%2,%3}, [%4];"
                 : "=r"(r0), "=r"(r1), "=r"(r2), "=r"(r3) : "r"(a));
}
__device__ __forceinline__ void mma16816(float* c, const uint32_t* a, uint32_t b0, uint32_t b1) {
    asm volatile(
        "mma.sync.aligned.m16n8k16.row.col.f32.bf16.bf16.f32 "
        "{%0,%1,%2,%3}, {%4,%5,%6,%7}, {%8,%9}, {%0,%1,%2,%3};"
        : "+f"(c[0]), "+f"(c[1]), "+f"(c[2]), "+f"(c[3])
        : "r"(a[0]), "r"(a[1]), "r"(a[2]), "r"(a[3]), "r"(b0), "r"(b1));
}

// ---------------- main attention kernel ----------------
__global__ void __launch_bounds__(NTH, 2)
attn_mma_kernel(const float* __restrict__ q, const float* __restrict__ k,
                const float* __restrict__ v, float* __restrict__ out,
                float* __restrict__ attn)
{
    extern __shared__ char smem[];
    const uint32_t sb = s2u(smem);
    const int tid = threadIdx.x;
    const int w = tid >> 5, lane = tid & 31;
    const int wr = w >> 1;       // row block (16 rows)
    const int wc = w & 1;        // key-half (32 keys)
    const int quad = lane >> 2, qlane = lane & 3;
    const int qt = blockIdx.x, b = blockIdx.y;
    const int qbase = qt * TQ;

    // ---- load Q tile -> bf16 hi/lo smem ----
    {
        const float* qg = q + ((size_t)(b * SS + qbase)) * DDIM;
        #pragma unroll
        for (int it = 0; it < 4; ++it) {
            int idx = tid + it * NTH;
            int row = idx >> 4, d4 = (idx & 15) << 2;
            float4 qv = *(const float4*)(qg + row * DDIM + d4);
            uint32_t h01, l01, h23, l23;
            split2(qv.x, qv.y, h01, l01);
            split2(qv.z, qv.w, h23, l23);
            *(uint2*)(smem + OQHI + row * RS + d4 * 2) = make_uint2(h01, h23);
            *(uint2*)(smem + OQLO + row * RS + d4 * 2) = make_uint2(l01, l23);
        }
    }
    __syncthreads();

    // ---- Q fragments (cached in registers for entire CTA lifetime) ----
    uint32_t qh[4][4], ql[4][4];
    {
        uint32_t arow = (uint32_t)(wr * 16 + (lane & 15)) * RS + (uint32_t)(lane >> 4) * 16;
        #pragma unroll
        for (int ks = 0; ks < 4; ++ks) {
            ldm4(qh[ks][0], qh[ks][1], qh[ks][2], qh[ks][3], sb + OQHI + arow + ks * 32);
            ldm4(ql[ks][0], ql[ks][1], ql[ks][2], ql[ks][3], sb + OQLO + arow + ks * 32);
        }
    }

    float O[8][4];
    #pragma unroll
    for (int j = 0; j < 8; ++j)
        #pragma unroll
        for (int i = 0; i < 4; ++i) O[j][i] = 0.f;
    float lsum0 = 0.f, lsum1 = 0.f;
    const float CEXP = 0.18033688011112042f;  // (1/8)*log2(e)

    // B-frag lane base addresses (byte offsets from sb added per use)
    // S (K as n-major B): keys = wc*32 + (lane>>4)*8 + (lane&7); col half = ((lane>>3)&1)*16B
    uint32_t kaddr = sb + (uint32_t)(wc * 32 + ((lane >> 4) << 3) + (lane & 7)) * RS
                        + (uint32_t)((lane >> 3) & 1) * 16;
    // PV (V row-major via ldmatrix.trans): rows = wc*32 + ((lane>>3)&1)*8 + (lane&7); dcol = (lane>>4)*16B
    uint32_t vaddr = sb + (uint32_t)(wc * 32 + (((lane >> 3) & 1) << 3) + (lane & 7)) * RS
                        + (uint32_t)(lane >> 4) * 16;

    // attn row pointers (cols advance by kbase per tile)
    float* arow0 = attn + ((size_t)(b * SS + qbase + wr * 16 + quad)) * SS + wc * 32 + 2 * qlane;
    float* arow1 = arow0 + 8 * (size_t)SS;

    for (int kt = 0; kt < NKT; ++kt) {
        const int kbase = kt * TK;
        __syncthreads();   // all PV reads of previous tile done

        // ---- load K,V tiles -> bf16 hi/lo smem ----
        {
            const float* kg = k + ((size_t)(b * SS + kbase)) * DDIM;
            const float* vg = v + ((size_t)(b * SS + kbase)) * DDIM;
            #pragma unroll
            for (int it = 0; it < 4; ++it) {
                int idx = tid + it * NTH;
                int row = idx >> 4, d4 = (idx & 15) << 2;
                float4 kv = *(const float4*)(kg + row * DDIM + d4);
                uint32_t h01, l01, h23, l23;
                split2(kv.x, kv.y, h01, l01);
                split2(kv.z, kv.w, h23, l23);
                *(uint2*)(smem + OKHI + row * RS + d4 * 2) = make_uint2(h01, h23);
                *(uint2*)(smem + OKLO + row * RS + d4 * 2) = make_uint2(l01, l23);
                float4 vv = *(const float4*)(vg + row * DDIM + d4);
                split2(vv.x, vv.y, h01, l01);
                split2(vv.z, vv.w, h23, l23);
                *(uint2*)(smem + OVHI + row * RS + d4 * 2) = make_uint2(h01, h23);
                *(uint2*)(smem + OVLO + row * RS + d4 * 2) = make_uint2(l01, l23);
            }
        }
        __syncthreads();

        // ---- S = QK^T with 3-term split ----
        float c[4][4];
        #pragma unroll
        for (int j = 0; j < 4; ++j)
            #pragma unroll
            for (int i = 0; i < 4; ++i) c[j][i] = 0.f;

        #pragma unroll
        for (int ks = 0; ks < 4; ++ks) {
            #pragma unroll
            for (int half = 0; half < 2; ++half) {
                uint32_t bh0, bh1, bh2, bh3, bl0, bl1, bl2, bl3;
                uint32_t off = (uint32_t)ks * 32 + (uint32_t)half * (16 * RS);
                ldm4(bh0, bh1, bh2, bh3, kaddr + OKHI + off);
                ldm4(bl0, bl1, bl2, bl3, kaddr + OKLO + off);
                int j0 = 2 * half;
                mma16816(c[j0], qh[ks], bh0, bh1);
                mma16816(c[j0], qh[ks], bl0, bl1);
                mma16816(c[j0], ql[ks], bh0, bh1);
                mma16816(c[j0 + 1], qh[ks], bh2, bh3);
                mma16816(c[j0 + 1], qh[ks], bl2, bl3);
                mma16816(c[j0 + 1], ql[ks], bh2, bh3);
            }
        }

        // ---- exp (overwrite c with e), attn STG, row-sum partials ----
        #pragma unroll
        for (int j = 0; j < 4; ++j) {
            #pragma unroll
            for (int i = 0; i < 4; ++i) c[j][i] = exp2f(c[j][i] * CEXP);
            lsum0 += c[j][0] + c[j][1];
            lsum1 += c[j][2] + c[j][3];
            float2 e01 = make_float2(c[j][0], c[j][1]);
            float2 e23 = make_float2(c[j][2], c[j][3]);
            *(float2*)(arow0 + kbase + 8 * j) = e01;
            *(float2*)(arow1 + kbase + 8 * j) = e23;
        }

        // ---- O += P V with 3-term split (A-frags straight from e registers) ----
        #pragma unroll
        for (int ks2 = 0; ks2 < 2; ++ks2) {
            int t2 = 2 * ks2;
            uint32_t ah[4], al[4];
            ah[0] = packbf(c[t2][0], c[t2][1]);
            ah[1] = packbf(c[t2][2], c[t2][3]);
            ah[2] = packbf(c[t2 + 1][0], c[t2 + 1][1]);
            ah[3] = packbf(c[t2 + 1][2], c[t2 + 1][3]);
            #pragma unroll
            for (int i = 0; i < 4; ++i) {
                int jt = t2 + (i >> 1);
                int bbase = (i & 1) * 2;
                float flo = c[jt][bbase]     - __uint_as_float(ah[i] << 16);
                float fhi = c[jt][bbase + 1] - __uint_as_float(ah[i] & 0xFFFF0000u);
                al[i] = packbf(flo, fhi);
            }
            uint32_t va = vaddr + OVHI + (uint32_t)ks2 * (16 * RS);
            uint32_t vb = vaddr + OVLO + (uint32_t)ks2 * (16 * RS);
            #pragma unroll
            for (int m = 0; m < 4; ++m) {
                uint32_t bh0, bh1, bh2, bh3, bl0, bl1, bl2, bl3;
                ldm4t(bh0, bh1, bh2, bh3, va + m * 32);
                ldm4t(bl0, bl1, bl2, bl3, vb + m * 32);
                mma16816(O[2 * m],     ah, bh0, bh1);
                mma16816(O[2 * m],     ah, bl0, bl1);
                mma16816(O[2 * m],     al, bh0, bh1);
                mma16816(O[2 * m + 1], ah, bh2, bh3);
                mma16816(O[2 * m + 1], ah, bl2, bl3);
                mma16816(O[2 * m + 1], al, bh2, bh3);
            }
        }
    }

    // ---- row-sum reduction across quad lanes ----
    lsum0 += __shfl_xor_sync(0xFFFFFFFFu, lsum0, 1);
    lsum0 += __shfl_xor_sync(0xFFFFFFFFu, lsum0, 2);
    lsum1 += __shfl_xor_sync(0xFFFFFFFFu, lsum1, 1);
    lsum1 += __shfl_xor_sync(0xFFFFFFFFu, lsum1, 2);

    float* lbuf = (float*)(smem + OLBUF);
    float* linv = (float*)(smem + OLINV);
    float* ored = (float*)(smem + ORED);

    if (qlane == 0) {
        lbuf[wc * 64 + wr * 16 + quad]     = lsum0;
        lbuf[wc * 64 + wr * 16 + quad + 8] = lsum1;
    }
    if (wc == 1) {
        #pragma unroll
        for (int j = 0; j < 8; ++j) {
            *(float2*)(ored + (wr * 16 + quad) * 68 + 8 * j + 2 * qlane)     = make_float2(O[j][0], O[j][1]);
            *(float2*)(ored + (wr * 16 + quad + 8) * 68 + 8 * j + 2 * qlane) = make_float2(O[j][2], O[j][3]);
        }
    }
    __syncthreads();
    if (tid < 64) {
        float s = lbuf[tid] + lbuf[64 + tid];
        float inv = 1.0f / s;
        linv[tid] = inv;
        g_invl[(size_t)b * SS + qbase + tid] = inv;
    }
    __syncthreads();
    if (wc == 0) {
        int r0 = wr * 16 + quad, r1 = r0 + 8;
        float inv0 = linv[r0], inv1 = linv[r1];
        float* op0 = out + ((size_t)(b * SS + qbase + r0)) * DDIM + 2 * qlane;
        float* op1 = out + ((size_t)(b * SS + qbase + r1)) * DDIM + 2 * qlane;
        #pragma unroll
        for (int j = 0; j < 8; ++j) {
            float2 p01 = *(float2*)(ored + r0 * 68 + 8 * j + 2 * qlane);
            float2 p23 = *(float2*)(ored + r1 * 68 + 8 * j + 2 * qlane);
            *(float2*)(op0 + 8 * j) = make_float2((O[j][0] + p01.x) * inv0, (O[j][1] + p01.y) * inv0);
            *(float2*)(op1 + 8 * j) = make_float2((O[j][2] + p23.x) * inv1, (O[j][3] + p23.y) * inv1);
        }
    }
}

// ---------------- attn row rescale (DRAM-roofline, unchanged) ----------------
__global__ void __launch_bounds__(256)
attn_normalize_kernel(float* __restrict__ attn)
{
    size_t idx = (size_t)blockIdx.x * blockDim.x + threadIdx.x;  // float4 index
    size_t row = idx >> 9;
    float inv = g_invl[row];
    float4* p = (float4*)attn;
    float4 vv = p[idx];
    vv.x *= inv; vv.y *= inv; vv.z *= inv; vv.w *= inv;
    p[idx] = vv;
}

extern "C" void kernel_launch(void* const* d_in, const int* in_sizes, int n_in,
                              void* d_out, int out_size)
{
    const float* q = (const float*)d_in[0];
    const float* k = (const float*)d_in[1];
    const float* v = (const float*)d_in[2];
    float* out  = (float*)d_out;
    float* attn = out + (size_t)BB * SS * DDIM;

    cudaFuncSetAttribute(attn_mma_kernel,
                         cudaFuncAttributeMaxDynamicSharedMemorySize, SMEMSZ);

    dim3 grid(SS / TQ, BB);
    attn_mma_kernel<<<grid, NTH, SMEMSZ>>>(q, k, v, out, attn);

    size_t nq4 = (size_t)BB * SS * SS / 4;
    attn_normalize_kernel<<<(unsigned)(nq4 / 256), 256>>>(attn);
}

// round 4
// speedup vs baseline: 3.2171x; 1.0095x over previous
#include <cuda_runtime.h>
#include <cstdint>

#define BB 32
#define SS 2048
#define DDIM 64
#define TQ 64
#define TK 64
#define NKT 32
#define NTH 256

// bf16 tile row stride: 72 elems = 144 bytes (16B-aligned, ldmatrix conflict-free)
#define RS 144
// smem byte offsets
#define OQHI 0u
#define OQLO 9216u
#define OKHI 18432u
#define OKLO 27648u
#define OVHI 36864u
#define OVLO 46080u
#define SMEMSZ 55296u
// epilogue reduce area reuses the Q region [0, 18432)
#define ORED  0u        // fp32 [64][68] O partials
#define OLBUF 17408u    // fp32 [128] row-sum partials
#define OLINV 17920u    // fp32 [64] inverse row sums

// ---------------- helpers ----------------
__device__ __forceinline__ uint32_t s2u(const void* p) {
    uint32_t a;
    asm("{ .reg .u64 t; cvta.to.shared.u64 t, %1; cvt.u32.u64 %0, t; }" : "=r"(a) : "l"(p));
    return a;
}
// split pair (a,b) -> packed bf16x2 hi (a in low half) and packed lo residuals
__device__ __forceinline__ void split2(float a, float b, uint32_t& hi, uint32_t& lo) {
    uint32_t h;
    asm("cvt.rn.bf16x2.f32 %0, %1, %2;" : "=r"(h) : "f"(b), "f"(a));
    float fa = __uint_as_float(h << 16);
    float fb = __uint_as_float(h & 0xFFFF0000u);
    float la = a - fa, lb = b - fb;
    asm("cvt.rn.bf16x2.f32 %0, %1, %2;" : "=r"(lo) : "f"(lb), "f"(la));
    hi = h;
}
__device__ __forceinline__ uint32_t packbf(float lo_e, float hi_e) {
    uint32_t r;
    asm("cvt.rn.bf16x2.f32 %0, %1, %2;" : "=r"(r) : "f"(hi_e), "f"(lo_e));
    return r;
}
__device__ __forceinline__ void ldm4(uint32_t& r0, uint32_t& r1, uint32_t& r2, uint32_t& r3, uint32_t a) {
    asm volatile("ldmatrix.sync.aligned.m8n8.x4.shared.b16 {%0,%1,%2,%3}, [%4];"
                 : "=r"(r0), "=r"(r1), "=r"(r2), "=r"(r3) : "r"(a));
}
__device__ __forceinline__ void ldm4t(uint32_t& r0, uint32_t& r1, uint32_t& r2, uint32_t& r3, uint32_t a) {
    asm volatile("ldmatrix.sync.aligned.m8n8.x4.trans.shared.b16 {%0,%1,%2,%3}, [%4];"
                 : "=r"(r0), "=r"(r1), "=r"(r2), "=r"(r3) : "r"(a));
}
__device__ __forceinline__ void mma16816(float* c, const uint32_t* a, uint32_t b0, uint32_t b1) {
    asm volatile(
        "mma.sync.aligned.m16n8k16.row.col.f32.bf16.bf16.f32 "
        "{%0,%1,%2,%3}, {%4,%5,%6,%7}, {%8,%9}, {%0,%1,%2,%3};"
        : "+f"(c[0]), "+f"(c[1]), "+f"(c[2]), "+f"(c[3])
        : "r"(a[0]), "r"(a[1]), "r"(a[2]), "r"(a[3]), "r"(b0), "r"(b1));
}

// ---------------- main attention kernel ----------------
__global__ void __launch_bounds__(NTH, 2)
attn_mma_kernel(const float* __restrict__ q, const float* __restrict__ k,
                const float* __restrict__ v, float* __restrict__ out,
                float* __restrict__ attn)
{
    extern __shared__ char smem[];
    const uint32_t sb = s2u(smem);
    const int tid = threadIdx.x;
    const int w = tid >> 5, lane = tid & 31;
    const int wr = w >> 1;       // row block (16 rows)
    const int wc = w & 1;        // key-half (32 keys)
    const int quad = lane >> 2, qlane = lane & 3;
    const int qt = blockIdx.x, b = blockIdx.y;
    const int qbase = qt * TQ;

    // ---- load Q tile -> bf16 hi/lo smem ----
    {
        const float* qg = q + ((size_t)(b * SS + qbase)) * DDIM;
        #pragma unroll
        for (int it = 0; it < 4; ++it) {
            int idx = tid + it * NTH;
            int row = idx >> 4, d4 = (idx & 15) << 2;
            float4 qv = *(const float4*)(qg + row * DDIM + d4);
            uint32_t h01, l01, h23, l23;
            split2(qv.x, qv.y, h01, l01);
            split2(qv.z, qv.w, h23, l23);
            *(uint2*)(smem + OQHI + row * RS + d4 * 2) = make_uint2(h01, h23);
            *(uint2*)(smem + OQLO + row * RS + d4 * 2) = make_uint2(l01, l23);
        }
    }
    __syncthreads();

    // ---- Q fragments (cached in registers for entire CTA lifetime) ----
    uint32_t qh[4][4], ql[4][4];
    {
        uint32_t arow = (uint32_t)(wr * 16 + (lane & 15)) * RS + (uint32_t)(lane >> 4) * 16;
        #pragma unroll
        for (int ks = 0; ks < 4; ++ks) {
            ldm4(qh[ks][0], qh[ks][1], qh[ks][2], qh[ks][3], sb + OQHI + arow + ks * 32);
            ldm4(ql[ks][0], ql[ks][1], ql[ks][2], ql[ks][3], sb + OQLO + arow + ks * 32);
        }
    }

    float O[8][4];
    #pragma unroll
    for (int j = 0; j < 8; ++j)
        #pragma unroll
        for (int i = 0; i < 4; ++i) O[j][i] = 0.f;
    float lsum0 = 0.f, lsum1 = 0.f;
    const float CEXP = 0.18033688011112042f;  // (1/8)*log2(e)

    // B-frag lane base addresses
    uint32_t kaddr = sb + (uint32_t)(wc * 32 + ((lane >> 4) << 3) + (lane & 7)) * RS
                        + (uint32_t)((lane >> 3) & 1) * 16;
    uint32_t vaddr = sb + (uint32_t)(wc * 32 + (((lane >> 3) & 1) << 3) + (lane & 7)) * RS
                        + (uint32_t)(lane >> 4) * 16;

    // attn row pointers (cols advance by kbase per tile)
    float* arow0 = attn + ((size_t)(b * SS + qbase + wr * 16 + quad)) * SS + wc * 32 + 2 * qlane;
    float* arow1 = arow0 + 8 * (size_t)SS;

    for (int kt = 0; kt < NKT; ++kt) {
        const int kbase = kt * TK;
        __syncthreads();   // all PV reads of previous tile done

        // ---- load K,V tiles -> bf16 hi/lo smem ----
        {
            const float* kg = k + ((size_t)(b * SS + kbase)) * DDIM;
            const float* vg = v + ((size_t)(b * SS + kbase)) * DDIM;
            #pragma unroll
            for (int it = 0; it < 4; ++it) {
                int idx = tid + it * NTH;
                int row = idx >> 4, d4 = (idx & 15) << 2;
                float4 kv = *(const float4*)(kg + row * DDIM + d4);
                uint32_t h01, l01, h23, l23;
                split2(kv.x, kv.y, h01, l01);
                split2(kv.z, kv.w, h23, l23);
                *(uint2*)(smem + OKHI + row * RS + d4 * 2) = make_uint2(h01, h23);
                *(uint2*)(smem + OKLO + row * RS + d4 * 2) = make_uint2(l01, l23);
                float4 vv = *(const float4*)(vg + row * DDIM + d4);
                split2(vv.x, vv.y, h01, l01);
                split2(vv.z, vv.w, h23, l23);
                *(uint2*)(smem + OVHI + row * RS + d4 * 2) = make_uint2(h01, h23);
                *(uint2*)(smem + OVLO + row * RS + d4 * 2) = make_uint2(l01, l23);
            }
        }
        __syncthreads();

        // ---- S = QK^T with 3-term split ----
        float c[4][4];
        #pragma unroll
        for (int j = 0; j < 4; ++j)
            #pragma unroll
            for (int i = 0; i < 4; ++i) c[j][i] = 0.f;

        #pragma unroll
        for (int ks = 0; ks < 4; ++ks) {
            #pragma unroll
            for (int half = 0; half < 2; ++half) {
                uint32_t bh0, bh1, bh2, bh3, bl0, bl1, bl2, bl3;
                uint32_t off = (uint32_t)ks * 32 + (uint32_t)half * (16 * RS);
                ldm4(bh0, bh1, bh2, bh3, kaddr + OKHI + off);
                ldm4(bl0, bl1, bl2, bl3, kaddr + OKLO + off);
                int j0 = 2 * half;
                mma16816(c[j0], qh[ks], bh0, bh1);
                mma16816(c[j0], qh[ks], bl0, bl1);
                mma16816(c[j0], ql[ks], bh0, bh1);
                mma16816(c[j0 + 1], qh[ks], bh2, bh3);
                mma16816(c[j0 + 1], qh[ks], bl2, bl3);
                mma16816(c[j0 + 1], ql[ks], bh2, bh3);
            }
        }

        // ---- exp (overwrite c with e), attn STG (unnormalized), row-sum partials ----
        #pragma unroll
        for (int j = 0; j < 4; ++j) {
            #pragma unroll
            for (int i = 0; i < 4; ++i) c[j][i] = exp2f(c[j][i] * CEXP);
            lsum0 += c[j][0] + c[j][1];
            lsum1 += c[j][2] + c[j][3];
            float2 e01 = make_float2(c[j][0], c[j][1]);
            float2 e23 = make_float2(c[j][2], c[j][3]);
            *(float2*)(arow0 + kbase + 8 * j) = e01;
            *(float2*)(arow1 + kbase + 8 * j) = e23;
        }

        // ---- O += P V with 3-term split (A-frags straight from e registers) ----
        #pragma unroll
        for (int ks2 = 0; ks2 < 2; ++ks2) {
            int t2 = 2 * ks2;
            uint32_t ah[4], al[4];
            ah[0] = packbf(c[t2][0], c[t2][1]);
            ah[1] = packbf(c[t2][2], c[t2][3]);
            ah[2] = packbf(c[t2 + 1][0], c[t2 + 1][1]);
            ah[3] = packbf(c[t2 + 1][2], c[t2 + 1][3]);
            #pragma unroll
            for (int i = 0; i < 4; ++i) {
                int jt = t2 + (i >> 1);
                int bbase = (i & 1) * 2;
                float flo = c[jt][bbase]     - __uint_as_float(ah[i] << 16);
                float fhi = c[jt][bbase + 1] - __uint_as_float(ah[i] & 0xFFFF0000u);
                al[i] = packbf(flo, fhi);
            }
            uint32_t va = vaddr + OVHI + (uint32_t)ks2 * (16 * RS);
            uint32_t vb = vaddr + OVLO + (uint32_t)ks2 * (16 * RS);
            #pragma unroll
            for (int m = 0; m < 4; ++m) {
                uint32_t bh0, bh1, bh2, bh3, bl0, bl1, bl2, bl3;
                ldm4t(bh0, bh1, bh2, bh3, va + m * 32);
                ldm4t(bl0, bl1, bl2, bl3, vb + m * 32);
                mma16816(O[2 * m],     ah, bh0, bh1);
                mma16816(O[2 * m],     ah, bl0, bl1);
                mma16816(O[2 * m],     al, bh0, bh1);
                mma16816(O[2 * m + 1], ah, bh2, bh3);
                mma16816(O[2 * m + 1], ah, bl2, bl3);
                mma16816(O[2 * m + 1], al, bh2, bh3);
            }
        }
    }

    // ---- row-sum reduction across quad lanes ----
    lsum0 += __shfl_xor_sync(0xFFFFFFFFu, lsum0, 1);
    lsum0 += __shfl_xor_sync(0xFFFFFFFFu, lsum0, 2);
    lsum1 += __shfl_xor_sync(0xFFFFFFFFu, lsum1, 1);
    lsum1 += __shfl_xor_sync(0xFFFFFFFFu, lsum1, 2);

    float* lbuf = (float*)(smem + OLBUF);
    float* linv = (float*)(smem + OLINV);
    float* ored = (float*)(smem + ORED);

    if (qlane == 0) {
        lbuf[wc * 64 + wr * 16 + quad]     = lsum0;
        lbuf[wc * 64 + wr * 16 + quad + 8] = lsum1;
    }
    if (wc == 1) {
        #pragma unroll
        for (int j = 0; j < 8; ++j) {
            *(float2*)(ored + (wr * 16 + quad) * 68 + 8 * j + 2 * qlane)     = make_float2(O[j][0], O[j][1]);
            *(float2*)(ored + (wr * 16 + quad + 8) * 68 + 8 * j + 2 * qlane) = make_float2(O[j][2], O[j][3]);
        }
    }
    __syncthreads();
    if (tid < 64) {
        float s = lbuf[tid] + lbuf[64 + tid];
        linv[tid] = 1.0f / s;
    }
    __syncthreads();

    // ---- O epilogue: reduce halves, normalize, store ----
    if (wc == 0) {
        int r0 = wr * 16 + quad, r1 = r0 + 8;
        float inv0 = linv[r0], inv1 = linv[r1];
        float* op0 = out + ((size_t)(b * SS + qbase + r0)) * DDIM + 2 * qlane;
        float* op1 = out + ((size_t)(b * SS + qbase + r1)) * DDIM + 2 * qlane;
        #pragma unroll
        for (int j = 0; j < 8; ++j) {
            float2 p01 = *(float2*)(ored + r0 * 68 + 8 * j + 2 * qlane);
            float2 p23 = *(float2*)(ored + r1 * 68 + 8 * j + 2 * qlane);
            *(float2*)(op0 + 8 * j) = make_float2((O[j][0] + p01.x) * inv0, (O[j][1] + p01.y) * inv0);
            *(float2*)(op1 + 8 * j) = make_float2((O[j][2] + p23.x) * inv1, (O[j][3] + p23.y) * inv1);
        }
    }

    // ---- fused attn normalize tail: rescale this CTA's own 64 rows ----
    // Lines were just written by this CTA -> still L2-resident; RMW served
    // from L2, DRAM sees attn only on final eviction.
    {
        float4* abase = (float4*)(attn + ((size_t)(b * SS + qbase)) * SS);
        #pragma unroll 4
        for (int it = 0; it < 128; ++it) {
            int idx = tid + it * NTH;       // 0..32767 float4s
            int row = idx >> 9;             // 512 float4 per row
            int c4  = idx & 511;
            float inv = linv[row];
            float4* p = abase + (size_t)row * (SS / 4) + c4;
            float4 vv = *p;
            vv.x *= inv; vv.y *= inv; vv.z *= inv; vv.w *= inv;
            *p = vv;
        }
    }
}

extern "C" void kernel_launch(void* const* d_in, const int* in_sizes, int n_in,
                              void* d_out, int out_size)
{
    const float* q = (const float*)d_in[0];
    const float* k = (const float*)d_in[1];
    const float* v = (const float*)d_in[2];
    float* out  = (float*)d_out;
    float* attn = out + (size_t)BB * SS * DDIM;

    cudaFuncSetAttribute(attn_mma_kernel,
                         cudaFuncAttributeMaxDynamicSharedMemorySize, SMEMSZ);

    dim3 grid(SS / TQ, BB);
    attn_mma_kernel<<<grid, NTH, SMEMSZ>>>(q, k, v, out, attn);
}

// round 6
// speedup vs baseline: 3.3558x; 1.0431x over previous
#include <cuda_runtime.h>
#include <cstdint>

#define BB 32
#define SS 2048
#define DDIM 64
#define TQ 64
#define TK 64
#define NKT 32
#define NTH 256

// bf16 tile row stride: 72 elems = 144 bytes (16B-aligned, ldmatrix conflict-free)
#define RS 144
// smem byte offsets
#define OQHI 0u
#define OQLO 9216u
#define OKHI 18432u
#define OKLO 27648u
#define OVHI 36864u
#define OVLO 46080u
#define ORAWK 55296u          // raw f32 K stage (16 KB)
#define ORAWV 71680u          // raw f32 V stage (16 KB)
#define SMEMSZ 88064u
// epilogue reduce area reuses the Q region [0, 18432)
#define ORED  0u        // fp32 [64][68] O partials
#define OLBUF 17408u    // fp32 [128] row-sum partials
#define OLINV 17920u    // fp32 [64] inverse row sums

// ---------------- helpers ----------------
__device__ __forceinline__ uint32_t s2u(const void* p) {
    uint32_t a;
    asm("{ .reg .u64 t; cvta.to.shared.u64 t, %1; cvt.u32.u64 %0, t; }" : "=r"(a) : "l"(p));
    return a;
}
__device__ __forceinline__ void split2(float a, float b, uint32_t& hi, uint32_t& lo) {
    uint32_t h;
    asm("cvt.rn.bf16x2.f32 %0, %1, %2;" : "=r"(h) : "f"(b), "f"(a));
    float fa = __uint_as_float(h << 16);
    float fb = __uint_as_float(h & 0xFFFF0000u);
    float la = a - fa, lb = b - fb;
    asm("cvt.rn.bf16x2.f32 %0, %1, %2;" : "=r"(lo) : "f"(lb), "f"(la));
    hi = h;
}
__device__ __forceinline__ uint32_t packbf(float lo_e, float hi_e) {
    uint32_t r;
    asm("cvt.rn.bf16x2.f32 %0, %1, %2;" : "=r"(r) : "f"(hi_e), "f"(lo_e));
    return r;
}
__device__ __forceinline__ void ldm4(uint32_t& r0, uint32_t& r1, uint32_t& r2, uint32_t& r3, uint32_t a) {
    asm volatile("ldmatrix.sync.aligned.m8n8.x4.shared.b16 {%0,%1,%2,%3}, [%4];"
                 : "=r"(r0), "=r"(r1), "=r"(r2), "=r"(r3) : "r"(a));
}
__device__ __forceinline__ void ldm4t(uint32_t& r0, uint32_t& r1, uint32_t& r2, uint32_t& r3, uint32_t a) {
    asm volatile("ldmatrix.sync.aligned.m8n8.x4.trans.shared.b16 {%0,%1,%2,%3}, [%4];"
                 : "=r"(r0), "=r"(r1), "=r"(r2), "=r"(r3) : "r"(a));
}
__device__ __forceinline__ void mma16816(float* c, const uint32_t* a, uint32_t b0, uint32_t b1) {
    asm volatile(
        "mma.sync.aligned.m16n8k16.row.col.f32.bf16.bf16.f32 "
        "{%0,%1,%2,%3}, {%4,%5,%6,%7}, {%8,%9}, {%0,%1,%2,%3};"
        : "+f"(c[0]), "+f"(c[1]), "+f"(c[2]), "+f"(c[3])
        : "r"(a[0]), "r"(a[1]), "r"(a[2]), "r"(a[3]), "r"(b0), "r"(b1));
}
__device__ __forceinline__ void cpa16(uint32_t dst, const float* src) {
    asm volatile("cp.async.cg.shared.global [%0], [%1], 16;" :: "r"(dst), "l"(src));
}
#define CPA_COMMIT() asm volatile("cp.async.commit_group;" ::: "memory")
#define CPA_WAIT0()  asm volatile("cp.async.wait_group 0;" ::: "memory")

// ---------------- main attention kernel ----------------
__global__ void __launch_bounds__(NTH, 2)
attn_mma_kernel(const float* __restrict__ q, const float* __restrict__ k,
                const float* __restrict__ v, float* __restrict__ out,
                float* __restrict__ attn)
{
    extern __shared__ char smem[];
    const uint32_t sb = s2u(smem);
    const int tid = threadIdx.x;
    const int w = tid >> 5, lane = tid & 31;
    const int wr = w >> 1;       // row block (16 rows)
    const int wc = w & 1;        // key-half (32 keys)
    const int quad = lane >> 2, qlane = lane & 3;
    const int qt = blockIdx.x, b = blockIdx.y;
    const int qbase = qt * TQ;

    // ---- load Q tile -> bf16 hi/lo smem ----
    {
        const float* qg = q + ((size_t)(b * SS + qbase)) * DDIM;
        #pragma unroll
        for (int it = 0; it < 4; ++it) {
            int idx = tid + it * NTH;
            int row = idx >> 4, d4 = (idx & 15) << 2;
            float4 qv = *(const float4*)(qg + row * DDIM + d4);
            uint32_t h01, l01, h23, l23;
            split2(qv.x, qv.y, h01, l01);
            split2(qv.z, qv.w, h23, l23);
            *(uint2*)(smem + OQHI + row * RS + d4 * 2) = make_uint2(h01, h23);
            *(uint2*)(smem + OQLO + row * RS + d4 * 2) = make_uint2(l01, l23);
        }
    }

    // ---- prefetch raw K/V tile 0 via cp.async ----
    {
        const float* kg = k + ((size_t)(b * SS)) * DDIM;
        const float* vg = v + ((size_t)(b * SS)) * DDIM;
        #pragma unroll
        for (int it = 0; it < 4; ++it) {
            int idx = tid + it * NTH;
            cpa16(sb + ORAWK + idx * 16, kg + idx * 4);
            cpa16(sb + ORAWV + idx * 16, vg + idx * 4);
        }
        CPA_COMMIT();
    }
    __syncthreads();

    // ---- Q fragments (registers, whole CTA lifetime) ----
    uint32_t qh[4][4], ql[4][4];
    {
        uint32_t arow = (uint32_t)(wr * 16 + (lane & 15)) * RS + (uint32_t)(lane >> 4) * 16;
        #pragma unroll
        for (int ks = 0; ks < 4; ++ks) {
            ldm4(qh[ks][0], qh[ks][1], qh[ks][2], qh[ks][3], sb + OQHI + arow + ks * 32);
            ldm4(ql[ks][0], ql[ks][1], ql[ks][2], ql[ks][3], sb + OQLO + arow + ks * 32);
        }
    }

    float O[8][4];
    #pragma unroll
    for (int j = 0; j < 8; ++j)
        #pragma unroll
        for (int i = 0; i < 4; ++i) O[j][i] = 0.f;
    float lsum0 = 0.f, lsum1 = 0.f;
    const float CEXP = 0.18033688011112042f;  // (1/8)*log2(e)

    uint32_t kaddr = sb + (uint32_t)(wc * 32 + ((lane >> 4) << 3) + (lane & 7)) * RS
                        + (uint32_t)((lane >> 3) & 1) * 16;
    uint32_t vaddr = sb + (uint32_t)(wc * 32 + (((lane >> 3) & 1) << 3) + (lane & 7)) * RS
                        + (uint32_t)(lane >> 4) * 16;

    float* arow0 = attn + ((size_t)(b * SS + qbase + wr * 16 + quad)) * SS + wc * 32 + 2 * qlane;
    float* arow1 = arow0 + 8 * (size_t)SS;

    for (int kt = 0; kt < NKT; ++kt) {
        const int kbase = kt * TK;
        CPA_WAIT0();
        __syncthreads();   // raw(kt) visible to all; PV reads of kt-1 done

        // ---- convert raw smem f32 -> bf16 hi/lo tiles ----
        #pragma unroll
        for (int it = 0; it < 4; ++it) {
            int idx = tid + it * NTH;
            int row = idx >> 4, d4 = (idx & 15) << 2;
            float4 kv = *(const float4*)(smem + ORAWK + idx * 16);
            uint32_t h01, l01, h23, l23;
            split2(kv.x, kv.y, h01, l01);
            split2(kv.z, kv.w, h23, l23);
            *(uint2*)(smem + OKHI + row * RS + d4 * 2) = make_uint2(h01, h23);
            *(uint2*)(smem + OKLO + row * RS + d4 * 2) = make_uint2(l01, l23);
            float4 vv = *(const float4*)(smem + ORAWV + idx * 16);
            split2(vv.x, vv.y, h01, l01);
            split2(vv.z, vv.w, h23, l23);
            *(uint2*)(smem + OVHI + row * RS + d4 * 2) = make_uint2(h01, h23);
            *(uint2*)(smem + OVLO + row * RS + d4 * 2) = make_uint2(l01, l23);
        }
        __syncthreads();

        // ---- prefetch next tile's raw K/V (overlaps with MMA phase) ----
        if (kt + 1 < NKT) {
            const float* kg = k + ((size_t)(b * SS + kbase + TK)) * DDIM;
            const float* vg = v + ((size_t)(b * SS + kbase + TK)) * DDIM;
            #pragma unroll
            for (int it = 0; it < 4; ++it) {
                int idx = tid + it * NTH;
                cpa16(sb + ORAWK + idx * 16, kg + idx * 4);
                cpa16(sb + ORAWV + idx * 16, vg + idx * 4);
            }
            CPA_COMMIT();
        }

        // ---- S = QK^T, 3-term split, ldmatrix software-pipelined ----
        float c[4][4];
        #pragma unroll
        for (int j = 0; j < 4; ++j)
            #pragma unroll
            for (int i = 0; i < 4; ++i) c[j][i] = 0.f;

        {
            uint32_t cbh[4], cbl[4], pbh[4], pbl[4];
            ldm4(cbh[0], cbh[1], cbh[2], cbh[3], kaddr + OKHI);
            ldm4(cbl[0], cbl[1], cbl[2], cbl[3], kaddr + OKLO);
            #pragma unroll
            for (int gi = 0; gi < 8; ++gi) {
                int ks = gi >> 1, half = gi & 1;
                if (gi < 7) {
                    int ksn = (gi + 1) >> 1, hn = (gi + 1) & 1;
                    uint32_t offn = (uint32_t)ksn * 32 + (uint32_t)hn * (16 * RS);
                    ldm4(pbh[0], pbh[1], pbh[2], pbh[3], kaddr + OKHI + offn);
                    ldm4(pbl[0], pbl[1], pbl[2], pbl[3], kaddr + OKLO + offn);
                }
                int j0 = 2 * half;
                mma16816(c[j0], qh[ks], cbh[0], cbh[1]);
                mma16816(c[j0], qh[ks], cbl[0], cbl[1]);
                mma16816(c[j0], ql[ks], cbh[0], cbh[1]);
                mma16816(c[j0 + 1], qh[ks], cbh[2], cbh[3]);
                mma16816(c[j0 + 1], qh[ks], cbl[2], cbl[3]);
                mma16816(c[j0 + 1], ql[ks], cbh[2], cbh[3]);
                #pragma unroll
                for (int t = 0; t < 4; ++t) { cbh[t] = pbh[t]; cbl[t] = pbl[t]; }
            }
        }

        // ---- exp (overwrite c with e), attn STG (unnormalized), row sums ----
        #pragma unroll
        for (int j = 0; j < 4; ++j) {
            #pragma unroll
            for (int i = 0; i < 4; ++i) c[j][i] = exp2f(c[j][i] * CEXP);
            lsum0 += c[j][0] + c[j][1];
            lsum1 += c[j][2] + c[j][3];
            float2 e01 = make_float2(c[j][0], c[j][1]);
            float2 e23 = make_float2(c[j][2], c[j][3]);
            *(float2*)(arow0 + kbase + 8 * j) = e01;
            *(float2*)(arow1 + kbase + 8 * j) = e23;
        }

        // ---- O += P V, 3-term split (A-frags from e registers) ----
        #pragma unroll
        for (int ks2 = 0; ks2 < 2; ++ks2) {
            int t2 = 2 * ks2;
            uint32_t ah[4], al[4];
            ah[0] = packbf(c[t2][0], c[t2][1]);
            ah[1] = packbf(c[t2][2], c[t2][3]);
            ah[2] = packbf(c[t2 + 1][0], c[t2 + 1][1]);
            ah[3] = packbf(c[t2 + 1][2], c[t2 + 1][3]);
            #pragma unroll
            for (int i = 0; i < 4; ++i) {
                int jt = t2 + (i >> 1);
                int bbase = (i & 1) * 2;
                float flo = c[jt][bbase]     - __uint_as_float(ah[i] << 16);
                float fhi = c[jt][bbase + 1] - __uint_as_float(ah[i] & 0xFFFF0000u);
                al[i] = packbf(flo, fhi);
            }
            uint32_t va = vaddr + OVHI + (uint32_t)ks2 * (16 * RS);
            uint32_t vb = vaddr + OVLO + (uint32_t)ks2 * (16 * RS);
            #pragma unroll
            for (int m = 0; m < 4; ++m) {
                uint32_t bh0, bh1, bh2, bh3, bl0, bl1, bl2, bl3;
                ldm4t(bh0, bh1, bh2, bh3, va + m * 32);
                ldm4t(bl0, bl1, bl2, bl3, vb + m * 32);
                mma16816(O[2 * m],     ah, bh0, bh1);
                mma16816(O[2 * m],     ah, bl0, bl1);
                mma16816(O[2 * m],     al, bh0, bh1);
                mma16816(O[2 * m + 1], ah, bh2, bh3);
                mma16816(O[2 * m + 1], ah, bl2, bl3);
                mma16816(O[2 * m + 1], al, bh2, bh3);
            }
        }
    }

    // ---- row-sum reduction across quad lanes ----
    lsum0 += __shfl_xor_sync(0xFFFFFFFFu, lsum0, 1);
    lsum0 += __shfl_xor_sync(0xFFFFFFFFu, lsum0, 2);
    lsum1 += __shfl_xor_sync(0xFFFFFFFFu, lsum1, 1);
    lsum1 += __shfl_xor_sync(0xFFFFFFFFu, lsum1, 2);

    float* lbuf = (float*)(smem + OLBUF);
    float* linv = (float*)(smem + OLINV);
    float* ored = (float*)(smem + ORED);

    if (qlane == 0) {
        lbuf[wc * 64 + wr * 16 + quad]     = lsum0;
        lbuf[wc * 64 + wr * 16 + quad + 8] = lsum1;
    }
    if (wc == 1) {
        #pragma unroll
        for (int j = 0; j < 8; ++j) {
            *(float2*)(ored + (wr * 16 + quad) * 68 + 8 * j + 2 * qlane)     = make_float2(O[j][0], O[j][1]);
            *(float2*)(ored + (wr * 16 + quad + 8) * 68 + 8 * j + 2 * qlane) = make_float2(O[j][2], O[j][3]);
        }
    }
    __syncthreads();
    if (tid < 64) {
        float s = lbuf[tid] + lbuf[64 + tid];
        linv[tid] = 1.0f / s;
    }
    __syncthreads();

    // ---- O epilogue: reduce halves, normalize, store ----
    if (wc == 0) {
        int r0 = wr * 16 + quad, r1 = r0 + 8;
        float inv0 = linv[r0], inv1 = linv[r1];
        float* op0 = out + ((size_t)(b * SS + qbase + r0)) * DDIM + 2 * qlane;
        float* op1 = out + ((size_t)(b * SS + qbase + r1)) * DDIM + 2 * qlane;
        #pragma unroll
        for (int j = 0; j < 8; ++j) {
            float2 p01 = *(float2*)(ored + r0 * 68 + 8 * j + 2 * qlane);
            float2 p23 = *(float2*)(ored + r1 * 68 + 8 * j + 2 * qlane);
            *(float2*)(op0 + 8 * j) = make_float2((O[j][0] + p01.x) * inv0, (O[j][1] + p01.y) * inv0);
            *(float2*)(op1 + 8 * j) = make_float2((O[j][2] + p23.x) * inv1, (O[j][3] + p23.y) * inv1);
        }
    }

    // ---- fused attn normalize tail (L2-resident RMW of own rows) ----
    {
        float4* abase = (float4*)(attn + ((size_t)(b * SS + qbase)) * SS);
        #pragma unroll 8
        for (int it = 0; it < 128; ++it) {
            int idx = tid + it * NTH;       // 0..32767 float4s
            int row = idx >> 9;             // 512 float4 per row
            int c4  = idx & 511;
            float inv = linv[row];
            float4* p = abase + (size_t)row * (SS / 4) + c4;
            float4 vv = *p;
            vv.x *= inv; vv.y *= inv; vv.z *= inv; vv.w *= inv;
            *p = vv;
        }
    }
}

extern "C" void kernel_launch(void* const* d_in, const int* in_sizes, int n_in,
                              void* d_out, int out_size)
{
    const float* q = (const float*)d_in[0];
    const float* k = (const float*)d_in[1];
    const float* v = (const float*)d_in[2];
    float* out  = (float*)d_out;
    float* attn = out + (size_t)BB * SS * DDIM;

    cudaFuncSetAttribute(attn_mma_kernel,
                         cudaFuncAttributeMaxDynamicSharedMemorySize, SMEMSZ);

    dim3 grid(SS / TQ, BB);
    attn_mma_kernel<<<grid, NTH, SMEMSZ>>>(q, k, v, out, attn);
}